// round 16
// baseline (speedup 1.0000x reference)
#include <cuda_runtime.h>
#include <cuda_fp16.h>
#include <math.h>
#include <stdint.h>

#define BB 4
#define CC 256
#define NN 4096
#define LOG2E 1.4426950408889634f

// ---------------- scratch (__device__ globals; no allocs allowed) ----------
__device__ __half g_qh[(size_t)BB * NN * 64];   // [b][n][32 q_hi | 32 q_lo] (2 MB)
__device__ __half g_kh[(size_t)BB * NN * 64];   // [b][n][32 k_hi | 32 k_lo] (2 MB)
__device__ __half g_vh[(size_t)BB * CC * NN];   // [b][c][j] fp16 V (8 MB)
__device__ __half g_wvh[CC * CC];               // Wv hi (128 KB)
__device__ __half g_wvl[CC * CC];               // Wv lo (128 KB)
__device__ __half g_wqkh[64 * CC];              // [Wq*log2e;Wk] hi (32 KB)
__device__ __half g_wqkl[64 * CC];              // [Wq*log2e;Wk] lo (32 KB)

// ---------------- helpers ---------------------------------------------------
__device__ __forceinline__ uint32_t smem_u32(const void* p) {
    uint32_t a;
    asm("{ .reg .u64 t; cvta.to.shared.u64 t, %1; cvt.u32.u64 %0, t; }"
        : "=r"(a) : "l"(p));
    return a;
}
__device__ __forceinline__ void cp16(uint32_t dst, const void* src) {
    asm volatile("cp.async.cg.shared.global [%0], [%1], 16;" :: "r"(dst), "l"(src)
                 : "memory");
}
__device__ __forceinline__ void sts32(uint32_t a, uint32_t v) {
    asm volatile("st.shared.u32 [%0], %1;" :: "r"(a), "r"(v) : "memory");
}
__device__ __forceinline__ void sts128(uint32_t a, uint32_t r0, uint32_t r1,
                                       uint32_t r2, uint32_t r3) {
    asm volatile("st.shared.v4.b32 [%0], {%1,%2,%3,%4};"
                 :: "r"(a), "r"(r0), "r"(r1), "r"(r2), "r"(r3) : "memory");
}
__device__ __forceinline__ uint32_t swaddr(uint32_t base, int row, int u) {
    return base + row * 128 + (((u) ^ (row & 7)) << 4);
}
__device__ __forceinline__ void ldm_x4(uint32_t& r0, uint32_t& r1,
                                       uint32_t& r2, uint32_t& r3, uint32_t a) {
    asm volatile("ldmatrix.sync.aligned.m8n8.x4.shared.b16 {%0,%1,%2,%3}, [%4];"
                 : "=r"(r0), "=r"(r1), "=r"(r2), "=r"(r3) : "r"(a));
}
__device__ __forceinline__ void mma16816(float* d, const uint32_t* a,
                                         uint32_t b0, uint32_t b1) {
    asm volatile(
        "mma.sync.aligned.m16n8k16.row.col.f32.f16.f16.f32 "
        "{%0,%1,%2,%3}, {%4,%5,%6,%7}, {%8,%9}, {%0,%1,%2,%3};"
        : "+f"(d[0]), "+f"(d[1]), "+f"(d[2]), "+f"(d[3])
        : "r"(a[0]), "r"(a[1]), "r"(a[2]), "r"(a[3]), "r"(b0), "r"(b1));
}
__device__ __forceinline__ uint32_t pkh2(float a, float b) {
    __half2 h = __floats2half2_rn(a, b);
    return *reinterpret_cast<uint32_t*>(&h);
}
__device__ __forceinline__ uint32_t packh(__half a, __half b) {
    __half2 h = __halves2half2(a, b);
    return *reinterpret_cast<uint32_t*>(&h);
}
__device__ __forceinline__ float ex2(float x) {
    float r;
    asm("ex2.approx.f32 %0, %1;" : "=f"(r) : "f"(x));
    return r;
}

// conflict-free x chunk staging (proven round 14)
__device__ __forceinline__ void stage_x_chunk(
    const float* __restrict__ x, int b, int kc, int n0,
    uint32_t xhb, uint32_t xlb, int tid)
{
    const int n = tid & 127, khalf = tid >> 7;
    const float* xcol =
        x + ((size_t)b * CC + kc * 64 + khalf * 32) * NN + n0 + n;
#pragma unroll
    for (int oct = 0; oct < 4; oct++) {
        float f[8];
#pragma unroll
        for (int j = 0; j < 8; j++)
            f[j] = xcol[(size_t)(oct * 8 + j) * NN];
        uint32_t hh[4], ll[4];
#pragma unroll
        for (int p = 0; p < 4; p++) {
            __half h0 = __float2half_rn(f[2 * p]);
            __half h1 = __float2half_rn(f[2 * p + 1]);
            hh[p] = packh(h0, h1);
            ll[p] = pkh2(f[2 * p]     - __half2float(h0),
                         f[2 * p + 1] - __half2float(h1));
        }
        int u = khalf * 4 + oct;
        sts128(swaddr(xhb, n, u), hh[0], hh[1], hh[2], hh[3]);
        sts128(swaddr(xlb, n, u), ll[0], ll[1], ll[2], ll[3]);
    }
}

// ---------------------------------------------------------------------------
// wsplit_all: Wv, Wq (scaled by log2e), Wk  -> hi/lo fp16 in one launch
// ---------------------------------------------------------------------------
__global__ __launch_bounds__(256) void wsplit_all_kernel(
    const float* __restrict__ Wv, const float* __restrict__ Wq,
    const float* __restrict__ Wk)
{
    int e4 = blockIdx.x * 256 + threadIdx.x;   // 80 blocks -> 20480 float4
    float4 v;
    float scale = 1.f;
    __half* dsth;
    __half* dstl;
    int base;
    if (e4 < 16384) {
        v = ((const float4*)Wv)[e4];
        dsth = g_wvh; dstl = g_wvl; base = e4 * 4;
    } else if (e4 < 18432) {
        int l = e4 - 16384;
        v = ((const float4*)Wq)[l];
        dsth = g_wqkh; dstl = g_wqkl; base = l * 4;
        scale = LOG2E;
    } else {
        int l = e4 - 18432;
        v = ((const float4*)Wk)[l];
        dsth = g_wqkh; dstl = g_wqkl; base = 32 * CC + l * 4;
    }
    float f[4] = {v.x * scale, v.y * scale, v.z * scale, v.w * scale};
#pragma unroll
    for (int t = 0; t < 4; t++) {
        __half hi = __float2half_rn(f[t]);
        __half lo = __float2half_rn(f[t] - __half2float(hi));
        dsth[base + t] = hi;
        dstl[base + t] = lo;
    }
}

// ---------------------------------------------------------------------------
// proj_kernel: fused V + QK projections via split-fp16 mma (proven round 15)
// ---------------------------------------------------------------------------
#define PVW_SMEM (4 * 16384 + 256)

__global__ __launch_bounds__(256, 2) void proj_kernel(
    const float* __restrict__ x)
{
    extern __shared__ char dsm[];
    const int b = blockIdx.z, n0 = blockIdx.x * 128;
    const int path = blockIdx.y;               // 0,1 = V halves; 2 = QK
    const int tid = threadIdx.x, wid = tid >> 5, lane = tid & 31;
    const int wcc = wid >> 2, wn = wid & 3;

    if (path < 2) {
        const int c0 = path * 128;
        const uint32_t whb = (smem_u32(dsm) + 127) & ~127u;
        const uint32_t wlb = whb + 16384;
        const uint32_t xhb = wlb + 16384;
        const uint32_t xlb = xhb + 16384;

        float acc[4][4][4];
#pragma unroll
        for (int i = 0; i < 4; i++)
#pragma unroll
            for (int j = 0; j < 4; j++)
#pragma unroll
                for (int k = 0; k < 4; k++) acc[i][j][k] = 0.f;

        const int a_row = wcc * 64 + (lane & 15);
        const int a_uo  = lane >> 4;
        const int b_row = wn * 32 + (lane & 7) + ((lane >> 4) << 3);
        const int b_uo  = (lane >> 3) & 1;

        for (int kc = 0; kc < 4; kc++) {
            __syncthreads();
#pragma unroll
            for (int i = 0; i < 4; i++) {
                int e = tid + i * 256, row = e >> 3, u = e & 7;
                cp16(swaddr(whb, row, u),
                     g_wvh + (size_t)(c0 + row) * CC + kc * 64 + u * 8);
                cp16(swaddr(wlb, row, u),
                     g_wvl + (size_t)(c0 + row) * CC + kc * 64 + u * 8);
            }
            asm volatile("cp.async.commit_group;" ::: "memory");

            stage_x_chunk(x, b, kc, n0, xhb, xlb, tid);

            asm volatile("cp.async.wait_group 0;" ::: "memory");
            __syncthreads();

#pragma unroll
            for (int ks = 0; ks < 4; ks++) {
                uint32_t ah[4][4], al[4][4];
#pragma unroll
                for (int qt = 0; qt < 4; qt++) {
                    ldm_x4(ah[qt][0], ah[qt][1], ah[qt][2], ah[qt][3],
                           swaddr(whb, a_row + qt * 16, a_uo + ks * 2));
                    ldm_x4(al[qt][0], al[qt][1], al[qt][2], al[qt][3],
                           swaddr(wlb, a_row + qt * 16, a_uo + ks * 2));
                }
                uint32_t bh[4][2], bl[4][2];
#pragma unroll
                for (int nt2 = 0; nt2 < 2; nt2++) {
                    uint32_t r0, r1, r2, r3;
                    ldm_x4(r0, r1, r2, r3,
                           swaddr(xhb, b_row + nt2 * 16, b_uo + ks * 2));
                    bh[nt2 * 2][0] = r0;     bh[nt2 * 2][1] = r1;
                    bh[nt2 * 2 + 1][0] = r2; bh[nt2 * 2 + 1][1] = r3;
                    ldm_x4(r0, r1, r2, r3,
                           swaddr(xlb, b_row + nt2 * 16, b_uo + ks * 2));
                    bl[nt2 * 2][0] = r0;     bl[nt2 * 2][1] = r1;
                    bl[nt2 * 2 + 1][0] = r2; bl[nt2 * 2 + 1][1] = r3;
                }
#pragma unroll
                for (int qt = 0; qt < 4; qt++)
#pragma unroll
                    for (int nt = 0; nt < 4; nt++) {
                        mma16816(acc[qt][nt], ah[qt], bh[nt][0], bh[nt][1]);
                        mma16816(acc[qt][nt], al[qt], bh[nt][0], bh[nt][1]);
                        mma16816(acc[qt][nt], ah[qt], bl[nt][0], bl[nt][1]);
                    }
            }
        }

#pragma unroll
        for (int qt = 0; qt < 4; qt++)
#pragma unroll
            for (int nt = 0; nt < 4; nt++) {
                int c = c0 + wcc * 64 + qt * 16 + (lane >> 2);
                int n = n0 + wn * 32 + nt * 8 + 2 * (lane & 3);
                *(uint32_t*)(g_vh + ((size_t)b * CC + c) * NN + n) =
                    pkh2(acc[qt][nt][0], acc[qt][nt][1]);
                *(uint32_t*)(g_vh + ((size_t)b * CC + c + 8) * NN + n) =
                    pkh2(acc[qt][nt][2], acc[qt][nt][3]);
            }
    } else {
        const uint32_t whb = (smem_u32(dsm) + 127) & ~127u;
        const uint32_t wlb = whb + 8192;
        const uint32_t xhb = wlb + 8192;
        const uint32_t xlb = xhb + 16384;

        float acc[2][4][4];
#pragma unroll
        for (int i = 0; i < 2; i++)
#pragma unroll
            for (int j = 0; j < 4; j++)
#pragma unroll
                for (int k = 0; k < 4; k++) acc[i][j][k] = 0.f;

        const int a_row = wcc * 32 + (lane & 15);
        const int a_uo  = lane >> 4;
        const int b_row = wn * 32 + (lane & 7) + ((lane >> 4) << 3);
        const int b_uo  = (lane >> 3) & 1;

        for (int kc = 0; kc < 4; kc++) {
            __syncthreads();
#pragma unroll
            for (int i = 0; i < 2; i++) {
                int e = tid + i * 256, row = e >> 3, u = e & 7;
                cp16(swaddr(whb, row, u),
                     g_wqkh + (size_t)row * CC + kc * 64 + u * 8);
                cp16(swaddr(wlb, row, u),
                     g_wqkl + (size_t)row * CC + kc * 64 + u * 8);
            }
            asm volatile("cp.async.commit_group;" ::: "memory");

            stage_x_chunk(x, b, kc, n0, xhb, xlb, tid);

            asm volatile("cp.async.wait_group 0;" ::: "memory");
            __syncthreads();

#pragma unroll
            for (int ks = 0; ks < 4; ks++) {
                uint32_t ah[2][4], al[2][4];
#pragma unroll
                for (int qt = 0; qt < 2; qt++) {
                    ldm_x4(ah[qt][0], ah[qt][1], ah[qt][2], ah[qt][3],
                           swaddr(whb, a_row + qt * 16, a_uo + ks * 2));
                    ldm_x4(al[qt][0], al[qt][1], al[qt][2], al[qt][3],
                           swaddr(wlb, a_row + qt * 16, a_uo + ks * 2));
                }
                uint32_t bh[4][2], bl[4][2];
#pragma unroll
                for (int nt2 = 0; nt2 < 2; nt2++) {
                    uint32_t r0, r1, r2, r3;
                    ldm_x4(r0, r1, r2, r3,
                           swaddr(xhb, b_row + nt2 * 16, b_uo + ks * 2));
                    bh[nt2 * 2][0] = r0;     bh[nt2 * 2][1] = r1;
                    bh[nt2 * 2 + 1][0] = r2; bh[nt2 * 2 + 1][1] = r3;
                    ldm_x4(r0, r1, r2, r3,
                           swaddr(xlb, b_row + nt2 * 16, b_uo + ks * 2));
                    bl[nt2 * 2][0] = r0;     bl[nt2 * 2][1] = r1;
                    bl[nt2 * 2 + 1][0] = r2; bl[nt2 * 2 + 1][1] = r3;
                }
#pragma unroll
                for (int qt = 0; qt < 2; qt++)
#pragma unroll
                    for (int nt = 0; nt < 4; nt++) {
                        mma16816(acc[qt][nt], ah[qt], bh[nt][0], bh[nt][1]);
                        mma16816(acc[qt][nt], al[qt], bh[nt][0], bh[nt][1]);
                        mma16816(acc[qt][nt], ah[qt], bl[nt][0], bl[nt][1]);
                    }
            }
        }

#pragma unroll
        for (int qt = 0; qt < 2; qt++)
#pragma unroll
            for (int nt = 0; nt < 4; nt++) {
                int o_base = wcc * 32 + qt * 16 + (lane >> 2);
                int n_base = n0 + wn * 32 + nt * 8 + 2 * (lane & 3);
#pragma unroll
                for (int dd = 0; dd < 4; dd++) {
                    int o = o_base + ((dd >> 1) << 3);
                    int n = n_base + (dd & 1);
                    float a = acc[qt][nt][dd];
                    __half hi = __float2half_rn(a);
                    __half lo = __float2half_rn(a - __half2float(hi));
                    size_t base = ((size_t)b * NN + n) * 64;
                    if (o < 32) { g_qh[base + o] = hi;      g_qh[base + 32 + o] = lo; }
                    else        { g_kh[base + o - 32] = hi; g_kh[base + o] = lo; }
                }
            }
    }
}

// ---------------------------------------------------------------------------
// fattn: delayed-PV merged block. Per tile: [PV(jt-1) | S(jt)] in one barrier
// interval, then stats. 2 syncs/tile. V distance-2 (3 buffers), K single
// buffer (distance-1), ptile single. M/L in registers; pm/corr fp16 smem.
// exp2 domain (q pre-scaled by log2e in weights).
// ---------------------------------------------------------------------------
#define FA_SMEM 114816   // ptile 8K + K 8K + 3x V 32K + align slack

__device__ __forceinline__ void fa_load_k(uint32_t kbuf, int b, int jt, int tid)
{
    const __half* ksrc = g_kh + ((size_t)b * NN + jt * 64) * 64;
#pragma unroll
    for (int rr = 0; rr < 2; rr++) {
        int e = tid + rr * 256, row = e >> 3, u = e & 7;
        cp16(swaddr(kbuf, row, u), ksrc + (size_t)row * 64 + u * 8);
    }
}
__device__ __forceinline__ void fa_load_v(uint32_t vbuf, int b, int jt, int tid)
{
    const __half* vsrc = g_vh + (size_t)b * CC * NN + jt * 64;
#pragma unroll
    for (int rr = 0; rr < 8; rr++) {
        int e = tid + rr * 256, row = e >> 3, u = e & 7;
        cp16(swaddr(vbuf, row, u), vsrc + (size_t)row * NN + u * 8);
    }
}

__global__ __launch_bounds__(256, 2) void fattn_kernel(
    const float* __restrict__ x, float* __restrict__ out)
{
    extern __shared__ char dsm[];
    __shared__ alignas(8) float plS[128];         // [wh][row]
    __shared__ alignas(4) __half pmS[128];        // [wh][row]
    __shared__ alignas(4) __half corrS[64];       // per row, this tile

    const int b = blockIdx.z, q0 = blockIdx.x * 64;
    const int tid = threadIdx.x, w = tid >> 5, lane = tid & 31;
    const int wq = w & 3, wh = w >> 2;
    const uint32_t base = (smem_u32(dsm) + 127) & ~127u;
    const uint32_t ptile = base;
    const uint32_t kb    = base + 8192;
    const uint32_t vb[3] = {base + 16384, base + 49152, base + 81920};

    // ---- prologue: g1={Q->vb2, K0}, g2={V0}, g3={V1} ----
    {
        const __half* qsrc = g_qh + ((size_t)b * NN + q0) * 64;
#pragma unroll
        for (int rr = 0; rr < 2; rr++) {
            int e = tid + rr * 256, row = e >> 3, u = e & 7;
            cp16(swaddr(vb[2], row, u), qsrc + (size_t)row * 64 + u * 8);
        }
        fa_load_k(kb, b, 0, tid);
        asm volatile("cp.async.commit_group;" ::: "memory");
        fa_load_v(vb[0], b, 0, tid);
        asm volatile("cp.async.commit_group;" ::: "memory");
        fa_load_v(vb[1], b, 1, tid);
        asm volatile("cp.async.commit_group;" ::: "memory");
    }

    // lane roles (identical to round 15)
    const int arow = wq * 16 + (lane & 15);
    const int au   = lane >> 4;
    const int krow = wh * 32 + (lane & 7) + ((lane >> 4) << 3);
    const int ku   = (lane >> 3) & 1;
    const int varow = w * 32 + (lane & 15);
    const int vau   = lane >> 4;
    const int pbrow = (lane & 7) + ((lane >> 4) << 3);
    const int pbu   = (lane >> 3) & 1;
    const int r0    = lane >> 2;
    const int row0  = wq * 16 + r0;       // h = 0
    const int row1  = row0 + 8;           // h = 1
    const int qoff  = lane & 3;

    // Q fragments -> registers
    uint32_t qf[6][4];
    {
        asm volatile("cp.async.wait_group 2;" ::: "memory");   // g1 done
        __syncthreads();
        const int poa[3] = {0, 0, 4};
#pragma unroll
        for (int part = 0; part < 3; part++)
#pragma unroll
            for (int ks = 0; ks < 2; ks++)
                ldm_x4(qf[part * 2 + ks][0], qf[part * 2 + ks][1],
                       qf[part * 2 + ks][2], qf[part * 2 + ks][3],
                       swaddr(vb[2], arow, poa[part] + ks * 2 + au));
    }

    float acc[2][8][4];
#pragma unroll
    for (int i = 0; i < 2; i++)
#pragma unroll
        for (int j = 0; j < 8; j++)
#pragma unroll
            for (int k = 0; k < 4; k++) acc[i][j][k] = 0.f;
    float M[2] = {-1e30f, -1e30f}, L[2] = {0.f, 0.f};

    const int NTJ = NN / 64;   // 64
    for (int jt = 0; jt < NTJ; jt++) {
        asm volatile("cp.async.wait_group 1;" ::: "memory");   // K(jt),V(jt) in
        __syncthreads();                                       // (1)

        if (jt > 0) {
            // ---- L update for tile jt-1 (consistent redundant regs) ----
            {
                float c0 = __half2float(corrS[row0]);
                float c1 = __half2float(corrS[row1]);
                L[0] = L[0] * c0 + plS[row0] + plS[64 + row0];
                L[1] = L[1] * c1 + plS[row1] + plS[64 + row1];
            }
            // ---- acc rescale (skip when all corr == 1) + PV(jt-1) ----
            const __half2* c2 = (const __half2*)corrS;
            float2 ccv[8];
            bool anyc = false;
#pragma unroll
            for (int nf = 0; nf < 8; nf++) {
                ccv[nf] = __half22float2(c2[nf * 4 + qoff]);
                anyc = anyc || (ccv[nf].x != 1.f) || (ccv[nf].y != 1.f);
            }
            if (__any_sync(0xffffffffu, anyc)) {
#pragma unroll
                for (int nf = 0; nf < 8; nf++)
#pragma unroll
                    for (int ct = 0; ct < 2; ct++) {
                        acc[ct][nf][0] *= ccv[nf].x;
                        acc[ct][nf][1] *= ccv[nf].y;
                        acc[ct][nf][2] *= ccv[nf].x;
                        acc[ct][nf][3] *= ccv[nf].y;
                    }
            }
            const uint32_t vcur = vb[(jt - 1) % 3];
#pragma unroll
            for (int ks = 0; ks < 4; ks++) {
                uint32_t a0[4], a1[4];
                ldm_x4(a0[0], a0[1], a0[2], a0[3],
                       swaddr(vcur, varow,      vau + ks * 2));
                ldm_x4(a1[0], a1[1], a1[2], a1[3],
                       swaddr(vcur, varow + 16, vau + ks * 2));
#pragma unroll
                for (int qt = 0; qt < 4; qt++) {
                    uint32_t b0, b1, b2, b3;
                    ldm_x4(b0, b1, b2, b3,
                           swaddr(ptile, pbrow + qt * 16, pbu + ks * 2));
                    mma16816(acc[0][qt * 2],     a0, b0, b1);
                    mma16816(acc[0][qt * 2 + 1], a0, b2, b3);
                    mma16816(acc[1][qt * 2],     a1, b0, b1);
                    mma16816(acc[1][qt * 2 + 1], a1, b2, b3);
                }
            }
        }

        // ---- S(jt) ----
        float s[4][4];
#pragma unroll
        for (int i = 0; i < 4; i++)
#pragma unroll
            for (int k = 0; k < 4; k++) s[i][k] = 0.f;
        {
            const int pob[3] = {0, 4, 0};
#pragma unroll
            for (int part = 0; part < 3; part++)
#pragma unroll
                for (int ks = 0; ks < 2; ks++) {
#pragma unroll
                    for (int nt2 = 0; nt2 < 2; nt2++) {
                        uint32_t b0, b1, b2, b3;
                        ldm_x4(b0, b1, b2, b3,
                               swaddr(kb, krow + nt2 * 16,
                                      pob[part] + ks * 2 + ku));
                        mma16816(s[nt2 * 2],     qf[part * 2 + ks], b0, b1);
                        mma16816(s[nt2 * 2 + 1], qf[part * 2 + ks], b2, b3);
                    }
                }
        }

        // ---- partial row max (fp16, consistent) ----
#pragma unroll
        for (int h = 0; h < 2; h++) {
            float t = -1e30f;
#pragma unroll
            for (int nt = 0; nt < 4; nt++)
                t = fmaxf(t, fmaxf(s[nt][2 * h], s[nt][2 * h + 1]));
            t = fmaxf(t, __shfl_xor_sync(0xffffffffu, t, 1));
            t = fmaxf(t, __shfl_xor_sync(0xffffffffu, t, 2));
            if ((lane & 3) == 0)
                pmS[wh * 64 + wq * 16 + r0 + h * 8] = __float2half_rn(t);
        }
        __syncthreads();                                       // (2)

        // ---- stats: mn, corr, exp2, P write, pl sums ----
#pragma unroll
        for (int h = 0; h < 2; h++) {
            const int row = wq * 16 + r0 + h * 8;
            float pm0 = __half2float(pmS[row]);
            float pm1 = __half2float(pmS[64 + row]);
            float mn = fmaxf(M[h], fmaxf(pm0, pm1));
            float corr = ex2(M[h] - mn);
            M[h] = mn;
            float lp = 0.f;
#pragma unroll
            for (int nt = 0; nt < 4; nt++) {
                float p0 = ex2(s[nt][2 * h]     - mn);
                float p1 = ex2(s[nt][2 * h + 1] - mn);
                lp += p0 + p1;
                int col = wh * 32 + nt * 8 + 2 * (lane & 3);
                int byte = col * 2;
                sts32(swaddr(ptile, row, byte >> 4) + (byte & 15), pkh2(p0, p1));
            }
            lp += __shfl_xor_sync(0xffffffffu, lp, 1);
            lp += __shfl_xor_sync(0xffffffffu, lp, 2);
            if ((lane & 3) == 0) {
                plS[wh * 64 + row] = lp;
                if (wh == 0) corrS[row] = __float2half_rn(corr);
            }
        }

        // ---- prefetch: K(jt+1) dist-1 (own group), V(jt+2) dist-2 ----
        if (jt + 1 < NTJ) fa_load_k(kb, b, jt + 1, tid);
        asm volatile("cp.async.commit_group;" ::: "memory");
        if (jt + 2 < NTJ) fa_load_v(vb[(jt + 2) % 3], b, jt + 2, tid);
        asm volatile("cp.async.commit_group;" ::: "memory");
    }

    // ---- epilogue: final L update + PV(NTJ-1) + normalize + residual ----
    __syncthreads();
    {
        float c0 = __half2float(corrS[row0]);
        float c1 = __half2float(corrS[row1]);
        L[0] = L[0] * c0 + plS[row0] + plS[64 + row0];
        L[1] = L[1] * c1 + plS[row1] + plS[64 + row1];

        const __half2* c2 = (const __half2*)corrS;
        float2 ccv[8];
        bool anyc = false;
#pragma unroll
        for (int nf = 0; nf < 8; nf++) {
            ccv[nf] = __half22float2(c2[nf * 4 + qoff]);
            anyc = anyc || (ccv[nf].x != 1.f) || (ccv[nf].y != 1.f);
        }
        if (__any_sync(0xffffffffu, anyc)) {
#pragma unroll
            for (int nf = 0; nf < 8; nf++)
#pragma unroll
                for (int ct = 0; ct < 2; ct++) {
                    acc[ct][nf][0] *= ccv[nf].x;
                    acc[ct][nf][1] *= ccv[nf].y;
                    acc[ct][nf][2] *= ccv[nf].x;
                    acc[ct][nf][3] *= ccv[nf].y;
                }
        }
        const uint32_t vcur = vb[(NTJ - 1) % 3];
#pragma unroll
        for (int ks = 0; ks < 4; ks++) {
            uint32_t a0[4], a1[4];
            ldm_x4(a0[0], a0[1], a0[2], a0[3],
                   swaddr(vcur, varow,      vau + ks * 2));
            ldm_x4(a1[0], a1[1], a1[2], a1[3],
                   swaddr(vcur, varow + 16, vau + ks * 2));
#pragma unroll
            for (int qt = 0; qt < 4; qt++) {
                uint32_t b0, b1, b2, b3;
                ldm_x4(b0, b1, b2, b3,
                       swaddr(ptile, pbrow + qt * 16, pbu + ks * 2));
                mma16816(acc[0][qt * 2],     a0, b0, b1);
                mma16816(acc[0][qt * 2 + 1], a0, b2, b3);
                mma16816(acc[1][qt * 2],     a1, b0, b1);
                mma16816(acc[1][qt * 2 + 1], a1, b2, b3);
            }
        }
    }
    __syncthreads();                    // plS free to reuse
    if ((lane & 3) == 0 && wh == 0) {
        plS[row0] = L[0];
        plS[row1] = L[1];
    }
    __syncthreads();

    {
        const float2* l2 = (const float2*)plS;
#pragma unroll
        for (int nf = 0; nf < 8; nf++) {
            float2 lv = l2[nf * 4 + qoff];
            float inv0 = 1.f / lv.x, inv1 = 1.f / lv.y;
            int q = q0 + nf * 8 + 2 * qoff;
#pragma unroll
            for (int ct = 0; ct < 2; ct++) {
                int c = w * 32 + ct * 16 + (lane >> 2);
                size_t i00 = ((size_t)b * CC + c) * NN + q;
                float2 xr0 = *(const float2*)(x + i00);
                float2 o0;
                o0.x = acc[ct][nf][0] * inv0 + xr0.x;
                o0.y = acc[ct][nf][1] * inv1 + xr0.y;
                *(float2*)(out + i00) = o0;
                size_t i08 = i00 + (size_t)8 * NN;
                float2 xr1 = *(const float2*)(x + i08);
                float2 o1;
                o1.x = acc[ct][nf][2] * inv0 + xr1.x;
                o1.y = acc[ct][nf][3] * inv1 + xr1.y;
                *(float2*)(out + i08) = o1;
            }
        }
    }
}

// ---------------------------------------------------------------------------
extern "C" void kernel_launch(void* const* d_in, const int* in_sizes, int n_in,
                              void* d_out, int out_size)
{
    const float* x  = (const float*)d_in[0];
    const float* Wq = (const float*)d_in[1];
    const float* Wk = (const float*)d_in[2];
    const float* Wv = (const float*)d_in[3];
    float* out = (float*)d_out;

    cudaFuncSetAttribute(fattn_kernel,
                         cudaFuncAttributeMaxDynamicSharedMemorySize, FA_SMEM);
    cudaFuncSetAttribute(proj_kernel,
                         cudaFuncAttributeMaxDynamicSharedMemorySize, PVW_SMEM);

    wsplit_all_kernel<<<80, 256>>>(Wv, Wq, Wk);
    proj_kernel      <<<dim3(NN / 128, 3, BB), 256, PVW_SMEM>>>(x);
    fattn_kernel     <<<dim3(NN / 64, 1, BB), 256, FA_SMEM>>>(x, out);
}